// round 1
// baseline (speedup 1.0000x reference)
#include <cuda_runtime.h>
#include <math.h>

#define B_   128
#define S_   512
#define T_   36
#define STARTT 34
#define ENDT   35

// dynamic smem layout (in floats):
//  [0, 18432)        feats for this batch (S*T)
//  [18432, 19728)    transitions (36*36)
//  [19728, 19824)    e double-buffer: 2 x 48 (16B aligned stride)
//  [19824, 19826)    m double-buffer (pad to 19840)
//  [19840, 19904)    reduction scratch (64)
#define FE 0
#define TR 18432
#define EB 19728
#define MB 19824
#define RD 19840
#define SMEM_FLOATS 19904
#define SMEM_BYTES  (SMEM_FLOATS * 4)

__device__ float g_partial[B_];

__global__ void __launch_bounds__(64, 1)
crf_forward_kernel(const float* __restrict__ feats,
                   const float* __restrict__ transitions,
                   const int*   __restrict__ mask,
                   const int*   __restrict__ tags)
{
    extern __shared__ float sh[];
    const int tid = threadIdx.x;
    const int b   = blockIdx.x;
    const int jc  = (tid < T_) ? tid : 0;   // column owned by this thread (clamped for pad lanes)

    // ---- stage feats[b] (72KB) + transitions (5.2KB) into smem, coalesced ----
    {
        const float4* fsrc = (const float4*)(feats + (size_t)b * (S_ * T_));
        float4* fdst = (float4*)(sh + FE);
        #pragma unroll
        for (int i = 0; i < (S_ * T_ / 4) / 64; i++)   // 72 iters
            fdst[tid + i * 64] = fsrc[tid + i * 64];

        const float4* tsrc = (const float4*)transitions;
        float4* tdst = (float4*)(sh + TR);
        for (int i = tid; i < (T_ * T_ / 4); i += 64)  // 324 float4
            tdst[i] = tsrc[i];
    }

    // ---- sequence length (mask is a contiguous prefix) ----
    int lsum = 0;
    {
        const int* mrow = mask + b * S_;
        for (int i = tid; i < S_; i += 64) lsum += mrow[i];
    }
    ((int*)(sh + RD))[tid] = lsum;
    __syncthreads();
    int len = 0;
    #pragma unroll
    for (int i = 0; i < 64; i++) len += ((const int*)(sh + RD))[i];

    // ---- precompute E column in registers: Ecol[i] = exp(trans[i][jc]) ----
    float Ecol[T_];
    #pragma unroll
    for (int i = 0; i < T_; i++)
        Ecol[i] = __expf(sh[TR + i * T_ + jc]);

    // ---- init: alpha_j = feats[b,0,j] + trans[START,j] ----
    float alpha = sh[FE + jc] + sh[TR + STARTT * T_ + jc];
    if (tid == 0) sh[MB + 0] = alpha;      // center seed = alpha_0^(0)
    __syncthreads();
    float m = sh[MB + 0];
    int buf = 1;                           // start on buffer 1 (avoid racing the seed slot)

    // ---- forward scan: t = 1 .. len-1 ----
    for (int t = 1; t < len; t++) {
        const float f = sh[FE + t * T_ + jc];   // issue early (off critical path)
        const float c = m;                      // center (alpha_0, ~1-step lag: numerically safe)
        const float e = __expf(alpha - c);
        if (tid < T_) sh[EB + buf * 48 + tid] = e;
        if (tid == 0) sh[MB + buf] = alpha;     // publish alpha_0 of previous step
        __syncthreads();                        // the ONLY barrier per step
        m = sh[MB + buf];

        const float4* ev = (const float4*)(sh + EB + buf * 48);
        float s0 = 0.f, s1 = 0.f, s2 = 0.f, s3 = 0.f;
        #pragma unroll
        for (int q = 0; q < 9; q++) {
            const float4 v = ev[q];
            s0 = fmaf(v.x, Ecol[4 * q + 0], s0);
            s1 = fmaf(v.y, Ecol[4 * q + 1], s1);
            s2 = fmaf(v.z, Ecol[4 * q + 2], s2);
            s3 = fmaf(v.w, Ecol[4 * q + 3], s3);
        }
        const float s = (s0 + s1) + (s2 + s3);

        alpha = __logf(s) + c + f;              // log(0) = -inf handles START column exactly
        buf ^= 1;
    }

    // ---- forward score: logsumexp_j(alpha_j + trans[j,END]) ----
    {
        const float term = (tid < T_) ? __expf(alpha + sh[TR + jc * T_ + ENDT] - m) : 0.0f;
        sh[RD + tid] = term;
    }
    __syncthreads();
    float fwd = 0.0f;
    if (tid == 0) {
        float acc = 0.0f;
        #pragma unroll
        for (int i = 0; i < T_; i++) acc += sh[RD + i];
        fwd = __logf(acc) + m;
    }
    __syncthreads();   // protect RD before gold reuses it

    // ---- gold score (gathers from smem feats/trans) ----
    {
        const int* trow = tags + b * S_;
        float g = 0.0f;
        for (int t = tid; t < len; t += 64) {
            const int tg = trow[t];
            const int pv = (t == 0) ? STARTT : trow[t - 1];
            g += sh[FE + t * T_ + tg] + sh[TR + pv * T_ + tg];
        }
        sh[RD + tid] = g;
        __syncthreads();
        if (tid == 0) {
            float acc = 0.0f;
            #pragma unroll
            for (int i = 0; i < 64; i++) acc += sh[RD + i];
            acc += sh[TR + trow[len - 1] * T_ + ENDT];   // end_energy
            g_partial[b] = fwd - acc;
        }
    }
}

__global__ void crf_finalize_kernel(float* __restrict__ out)
{
    __shared__ float r[B_];
    const int tid = threadIdx.x;
    r[tid] = g_partial[tid];
    __syncthreads();
    #pragma unroll
    for (int off = B_ / 2; off > 0; off >>= 1) {
        if (tid < off) r[tid] += r[tid + off];
        __syncthreads();
    }
    if (tid == 0) out[0] = r[0] / (float)B_;
}

extern "C" void kernel_launch(void* const* d_in, const int* in_sizes, int n_in,
                              void* d_out, int out_size)
{
    const float* feats = (const float*)d_in[0];
    const float* trans = (const float*)d_in[1];
    const int*   mask  = (const int*)d_in[2];
    const int*   tags  = (const int*)d_in[3];

    cudaFuncSetAttribute((const void*)crf_forward_kernel,
                         cudaFuncAttributeMaxDynamicSharedMemorySize, SMEM_BYTES);
    crf_forward_kernel<<<B_, 64, SMEM_BYTES>>>(feats, trans, mask, tags);
    crf_finalize_kernel<<<1, B_>>>((float*)d_out);
}

// round 2
// speedup vs baseline: 1.4572x; 1.4572x over previous
#include <cuda_runtime.h>
#include <math.h>

#define B_   128
#define S_   512
#define T_   36
#define STARTT 34
#define ENDT   35

// dynamic smem layout (floats):
//  [0, 18432)        feats for this batch (S*T)
//  [18432, 19728)    transitions (36*36)
//  [19728, 19824)    p-vector double buffer: 2 x 48 (16B-aligned stride)
//  [19840, 19904)    reduction scratch (64)
#define FE 0
#define TR 18432
#define EB 19728
#define RD 19840
#define SMEM_FLOATS 19904
#define SMEM_BYTES  (SMEM_FLOATS * 4)

__device__ float g_partial[B_];
__device__ int   g_count = 0;

__device__ __forceinline__ unsigned long long ffma2(unsigned long long a,
                                                    unsigned long long b,
                                                    unsigned long long c) {
    unsigned long long d;
    asm("fma.rn.f32x2 %0, %1, %2, %3;" : "=l"(d) : "l"(a), "l"(b), "l"(c));
    return d;
}
__device__ __forceinline__ unsigned long long fadd2(unsigned long long a,
                                                    unsigned long long b) {
    unsigned long long d;
    asm("add.rn.f32x2 %0, %1, %2;" : "=l"(d) : "l"(a), "l"(b));
    return d;
}
__device__ __forceinline__ unsigned long long pack2(float lo, float hi) {
    unsigned long long d;
    asm("mov.b64 %0, {%1, %2};" : "=l"(d) : "f"(lo), "f"(hi));
    return d;
}
__device__ __forceinline__ void unpack2(unsigned long long v, float& lo, float& hi) {
    asm("mov.b64 {%0, %1}, %2;" : "=f"(lo), "=f"(hi) : "l"(v));
}

__global__ void __launch_bounds__(64, 1)
crf_kernel(const float* __restrict__ feats,
           const float* __restrict__ transitions,
           const int*   __restrict__ mask,
           const int*   __restrict__ tags,
           float*       __restrict__ out)
{
    extern __shared__ float sh[];
    const int tid = threadIdx.x;
    const int b   = blockIdx.x;
    const int jc  = (tid < T_) ? tid : 0;

    // ---- stage feats[b] (72KB) + transitions into smem, coalesced ----
    {
        const float4* fsrc = (const float4*)(feats + (size_t)b * (S_ * T_));
        float4* fdst = (float4*)(sh + FE);
        #pragma unroll
        for (int i = 0; i < (S_ * T_ / 4) / 64; i++)
            fdst[tid + i * 64] = fsrc[tid + i * 64];

        const float4* tsrc = (const float4*)transitions;
        float4* tdst = (float4*)(sh + TR);
        for (int i = tid; i < (T_ * T_ / 4); i += 64)
            tdst[i] = tsrc[i];
    }

    // ---- sequence length (mask is a contiguous prefix) ----
    int lsum = 0;
    {
        const int* mrow = mask + b * S_;
        for (int i = tid; i < S_; i += 64) lsum += mrow[i];
    }
    ((int*)(sh + RD))[tid] = lsum;
    __syncthreads();
    int len = 0;
    #pragma unroll
    for (int i = 0; i < 64; i++) len += ((const int*)(sh + RD))[i];

    // ---- precompute packed E column: E2[m] = (exp(tr[2m][jc]), exp(tr[2m+1][jc])) ----
    unsigned long long E2[18];
    #pragma unroll
    for (int m = 0; m < 18; m++) {
        float e0 = __expf(sh[TR + (2 * m)     * T_ + jc]);
        float e1 = __expf(sh[TR + (2 * m + 1) * T_ + jc]);
        E2[m] = pack2(e0, e1);
    }

    // ---- init: p_j = exp(feats[b,0,j] + trans[START,j]); START col -> exp(-1000)=0 ----
    float p = __expf(sh[FE + jc] + sh[TR + STARTT * T_ + jc]);
    int Ksum = 0;
    int buf  = 0;

    // ---- forward scan in linear domain with per-step power-of-two renorm ----
    for (int t = 1; t < len; t++) {
        const float f  = sh[FE + t * T_ + jc];
        const float ef = __expf(f);                     // off the critical path
        if (tid < T_) sh[EB + buf * 48 + tid] = p;
        __syncthreads();                                // the ONLY barrier per step

        const ulonglong2* ev = (const ulonglong2*)(sh + EB + buf * 48);
        ulonglong2 V[9];
        #pragma unroll
        for (int q = 0; q < 9; q++) V[q] = ev[q];

        // renorm factor from exponent bits of P0 (integer-only, parallel to the dot)
        unsigned int p0bits = (unsigned int)(V[0].x);
        int k = (int)((p0bits >> 23) & 0xFF) - 127;
        k = max(-64, min(64, k));
        Ksum += k;
        const float sc   = __int_as_float((unsigned)(127 - k) << 23);  // 2^-k
        const float efsc = ef * sc;

        unsigned long long acc[6] = {0ull, 0ull, 0ull, 0ull, 0ull, 0ull};
        #pragma unroll
        for (int m = 0; m < 18; m++) {
            unsigned long long pv = (m & 1) ? V[m >> 1].y : V[m >> 1].x;
            acc[m % 6] = ffma2(pv, E2[m], acc[m % 6]);
        }
        acc[0] = fadd2(acc[0], acc[3]);
        acc[1] = fadd2(acc[1], acc[4]);
        acc[2] = fadd2(acc[2], acc[5]);
        acc[0] = fadd2(acc[0], acc[1]);
        acc[0] = fadd2(acc[0], acc[2]);
        float lo, hi;
        unpack2(acc[0], lo, hi);
        p = (lo + hi) * efsc;
        buf ^= 1;
    }

    // ---- forward score: log(sum_j p_j * exp(trans[j,END])) + Ksum*ln2 ----
    {
        const float eend = __expf(sh[TR + jc * T_ + ENDT]);
        sh[RD + tid] = (tid < T_) ? p * eend : 0.0f;
    }
    __syncthreads();
    float fwd = 0.0f;
    if (tid == 0) {
        float acc = 0.0f;
        #pragma unroll
        for (int i = 0; i < T_; i++) acc += sh[RD + i];
        fwd = __logf(acc) + (float)Ksum * 0.6931471805599453f;
    }
    __syncthreads();   // protect RD before gold reuses it

    // ---- gold score ----
    {
        const int* trow = tags + b * S_;
        float g = 0.0f;
        for (int t = tid; t < len; t += 64) {
            const int tg = trow[t];
            const int pv = (t == 0) ? STARTT : trow[t - 1];
            g += sh[FE + t * T_ + tg] + sh[TR + pv * T_ + tg];
        }
        sh[RD + tid] = g;
        __syncthreads();
        if (tid == 0) {
            float acc = 0.0f;
            #pragma unroll
            for (int i = 0; i < 64; i++) acc += sh[RD + i];
            acc += sh[TR + trow[len - 1] * T_ + ENDT];   // end_energy
            g_partial[b] = fwd - acc;
        }
    }

    // ---- fused finalize: last block reduces all partials (deterministic order) ----
    __shared__ int lastflag;
    __threadfence();
    if (tid == 0) lastflag = (atomicAdd(&g_count, 1) == B_ - 1);
    __syncthreads();
    if (lastflag) {
        volatile const float* gp = g_partial;
        float v = gp[tid] + gp[tid + 64];
        sh[RD + tid] = v;
        __syncthreads();
        if (tid == 0) {
            float acc = 0.0f;
            #pragma unroll
            for (int i = 0; i < 64; i++) acc += sh[RD + i];
            out[0] = acc * (1.0f / (float)B_);
            g_count = 0;   // reset for the next graph replay
        }
    }
}

extern "C" void kernel_launch(void* const* d_in, const int* in_sizes, int n_in,
                              void* d_out, int out_size)
{
    const float* feats = (const float*)d_in[0];
    const float* trans = (const float*)d_in[1];
    const int*   mask  = (const int*)d_in[2];
    const int*   tags  = (const int*)d_in[3];

    cudaFuncSetAttribute((const void*)crf_kernel,
                         cudaFuncAttributeMaxDynamicSharedMemorySize, SMEM_BYTES);
    crf_kernel<<<B_, 64, SMEM_BYTES>>>(feats, trans, mask, tags, (float*)d_out);
}

// round 3
// speedup vs baseline: 1.5000x; 1.0293x over previous
#include <cuda_runtime.h>
#include <math.h>

#define B_   128
#define S_   512
#define T_   36
#define NS   34      // active states (START col always 0; END row/col inert)
#define STARTT 34
#define ENDT   35

// dynamic smem layout (floats):
//  [0, 18432)        exp(feats) for this batch (S*T)
//  [18432, 19728)    raw transitions (36*36)
//  [19728, 19824)    p-vector ping-pong: 2 x 48 (16B-aligned stride, 34 used + zero pad)
//  [19840, 19968)    reduction scratch (128)
//  [19968]           gold score
#define EF 0
#define TR 18432
#define PB 19728
#define RD 19840
#define GD 19968
#define SMEM_FLOATS 19972
#define SMEM_BYTES  (SMEM_FLOATS * 4)

__device__ float g_partial[B_];
__device__ int   g_count = 0;

__device__ __forceinline__ unsigned long long ffma2(unsigned long long a,
                                                    unsigned long long b,
                                                    unsigned long long c) {
    unsigned long long d;
    asm("fma.rn.f32x2 %0, %1, %2, %3;" : "=l"(d) : "l"(a), "l"(b), "l"(c));
    return d;
}
__device__ __forceinline__ unsigned long long fadd2(unsigned long long a,
                                                    unsigned long long b) {
    unsigned long long d;
    asm("add.rn.f32x2 %0, %1, %2;" : "=l"(d) : "l"(a), "l"(b));
    return d;
}
__device__ __forceinline__ unsigned long long pack2(float lo, float hi) {
    unsigned long long d;
    asm("mov.b64 %0, {%1, %2};" : "=l"(d) : "f"(lo), "f"(hi));
    return d;
}
__device__ __forceinline__ void unpack2(unsigned long long v, float& lo, float& hi) {
    asm("mov.b64 {%0, %1}, %2;" : "=f"(lo), "=f"(hi) : "l"(v));
}

__global__ void __launch_bounds__(128, 1)
crf_kernel(const float* __restrict__ feats,
           const float* __restrict__ transitions,
           const int*   __restrict__ mask,
           const int*   __restrict__ tags,
           float*       __restrict__ out)
{
    extern __shared__ float sh[];
    const int tid  = threadIdx.x;
    const int lane = tid & 31;
    const int wid  = tid >> 5;
    const int b    = blockIdx.x;

    // ---- stage exp(feats[b]) (72KB) + raw transitions into smem, coalesced ----
    {
        const float4* fsrc = (const float4*)(feats + (size_t)b * (S_ * T_));
        float4* fdst = (float4*)(sh + EF);
        #pragma unroll
        for (int i = 0; i < (S_ * T_ / 4) / 128; i++) {   // 36 iters
            float4 v = fsrc[tid + i * 128];
            v.x = __expf(v.x); v.y = __expf(v.y);
            v.z = __expf(v.z); v.w = __expf(v.w);
            fdst[tid + i * 128] = v;
        }
        const float4* tsrc = (const float4*)transitions;
        float4* tdst = (float4*)(sh + TR);
        for (int i = tid; i < (T_ * T_ / 4); i += 128)
            tdst[i] = tsrc[i];
        // zero-pad slots 34..47 of both ping-pong buffers (never rewritten)
        if (tid < 14) { sh[PB + 34 + tid] = 0.0f; sh[PB + 48 + 34 + tid] = 0.0f; }
    }

    // ---- sequence length (mask is a contiguous prefix) ----
    int lsum = 0;
    {
        const int* mrow = mask + b * S_;
        #pragma unroll
        for (int i = 0; i < 4; i++) lsum += mrow[tid + i * 128];
    }
    #pragma unroll
    for (int off = 16; off > 0; off >>= 1)
        lsum += __shfl_xor_sync(0xFFFFFFFFu, lsum, off);
    if (lane == 0) ((int*)(sh + RD))[wid] = lsum;
    __syncthreads();
    const int len = ((const int*)(sh + RD))[0] + ((const int*)(sh + RD))[1]
                  + ((const int*)(sh + RD))[2] + ((const int*)(sh + RD))[3];

    float fwd = 0.0f;

    if (wid == 0) {
        // =========== warp 0: forward scan (single-warp, syncwarp only) ===========
        const int l  = (lane < 17) ? lane : 16;   // clamp pad lanes (duplicate work)
        const int j0 = 2 * l, j1 = 2 * l + 1;

        // E registers, cross-packed:
        //  EA[m] = (exp(tr[2m][j0]),   exp(tr[2m+1][j1]))
        //  EB[m] = (exp(tr[2m][j1]),   exp(tr[2m+1][j0]))
        unsigned long long EA[17], EB[17];
        #pragma unroll
        for (int m = 0; m < 17; m++) {
            const float t00 = __expf(sh[TR + (2 * m)     * T_ + j0]);
            const float t01 = __expf(sh[TR + (2 * m)     * T_ + j1]);
            const float t10 = __expf(sh[TR + (2 * m + 1) * T_ + j0]);
            const float t11 = __expf(sh[TR + (2 * m + 1) * T_ + j1]);
            EA[m] = pack2(t00, t11);
            EB[m] = pack2(t01, t10);
        }

        // init: p_j = exp(feats[0,j]) * exp(tr[START,j])
        float2 pcur;
        pcur.x = sh[EF + j0] * __expf(sh[TR + STARTT * T_ + j0]);
        pcur.y = sh[EF + j1] * __expf(sh[TR + STARTT * T_ + j1]);
        if (lane < 17) *(float2*)(sh + PB + j0) = pcur;
        __syncwarp();

        int Ksum = 0;
        int buf  = 0;
        for (int t = 1; t < len; t++) {
            const ulonglong2* Vp = (const ulonglong2*)(sh + PB + buf * 48);
            ulonglong2 V[9];
            #pragma unroll
            for (int q = 0; q < 9; q++) V[q] = Vp[q];
            const float2 ef2 = *(const float2*)(sh + EF + t * T_ + j0);

            // power-of-two renorm from exponent bits of p_0 (integer path)
            const unsigned p0bits = (unsigned)(V[0].x & 0xFFFFFFFFull);
            int k = (int)((p0bits >> 23) & 0xFF) - 127;
            k = max(-64, min(64, k));
            Ksum += k;
            const float sc = __int_as_float((unsigned)(127 - k) << 23);  // 2^-k

            unsigned long long accA[3] = {0ull, 0ull, 0ull};
            unsigned long long accB[3] = {0ull, 0ull, 0ull};
            #pragma unroll
            for (int m = 0; m < 17; m++) {
                const unsigned long long pm = (m & 1) ? V[m >> 1].y : V[m >> 1].x;
                accA[m % 3] = ffma2(pm, EA[m], accA[m % 3]);
                accB[m % 3] = ffma2(pm, EB[m], accB[m % 3]);
            }
            const unsigned long long rA = fadd2(fadd2(accA[0], accA[1]), accA[2]);
            const unsigned long long rB = fadd2(fadd2(accB[0], accB[1]), accB[2]);
            float a0, a1, b0, b1;
            unpack2(rA, a0, a1);
            unpack2(rB, b0, b1);
            pcur.x = (a0 + b1) * ef2.x * sc;
            pcur.y = (a1 + b0) * ef2.y * sc;

            if (lane < 17) *(float2*)(sh + PB + (buf ^ 1) * 48 + j0) = pcur;
            __syncwarp();
            buf ^= 1;
        }

        // forward score: log(sum_j p_j * exp(tr[j][END])) + Ksum*ln2
        const float e0 = __expf(sh[TR + j0 * T_ + ENDT]);
        const float e1 = __expf(sh[TR + j1 * T_ + ENDT]);
        float contrib = (lane < 17) ? (pcur.x * e0 + pcur.y * e1) : 0.0f;
        #pragma unroll
        for (int off = 16; off > 0; off >>= 1)
            contrib += __shfl_xor_sync(0xFFFFFFFFu, contrib, off);
        fwd = __logf(contrib) + (float)Ksum * 0.6931471805599453f;
    } else {
        // =========== warps 1-3: gold score (concurrent with the scan) ===========
        const int*   trow = tags  + b * S_;
        const float* frow = feats + (size_t)b * (S_ * T_);
        float g = 0.0f;
        for (int t = tid - 32; t < len; t += 96) {
            const int tg = trow[t];
            const int pv = (t == 0) ? STARTT : trow[t - 1];
            g += __ldg(frow + t * T_ + tg) + sh[TR + pv * T_ + tg];
        }
        #pragma unroll
        for (int off = 16; off > 0; off >>= 1)
            g += __shfl_xor_sync(0xFFFFFFFFu, g, off);
        if (lane == 0) sh[RD + wid] = g;
        asm volatile("bar.sync 1, 96;" ::: "memory");
        if (tid == 32) {
            const float endE = sh[TR + trow[len - 1] * T_ + ENDT];
            sh[GD] = sh[RD + 1] + sh[RD + 2] + sh[RD + 3] + endE;
        }
    }

    __syncthreads();
    if (tid == 0) g_partial[b] = fwd - sh[GD];

    // ---- fused finalize: last block reduces all partials (deterministic) ----
    __shared__ int lastflag;
    __threadfence();
    if (tid == 0) lastflag = (atomicAdd(&g_count, 1) == B_ - 1);
    __syncthreads();
    if (lastflag) {
        volatile const float* gp = g_partial;
        sh[RD + tid] = gp[tid];
        __syncthreads();
        #pragma unroll
        for (int off = 64; off > 0; off >>= 1) {
            if (tid < off) sh[RD + tid] += sh[RD + tid + off];
            __syncthreads();
        }
        if (tid == 0) {
            out[0] = sh[RD] * (1.0f / (float)B_);
            g_count = 0;   // reset for next graph replay
        }
    }
}

extern "C" void kernel_launch(void* const* d_in, const int* in_sizes, int n_in,
                              void* d_out, int out_size)
{
    const float* feats = (const float*)d_in[0];
    const float* trans = (const float*)d_in[1];
    const int*   mask  = (const int*)d_in[2];
    const int*   tags  = (const int*)d_in[3];

    cudaFuncSetAttribute((const void*)crf_kernel,
                         cudaFuncAttributeMaxDynamicSharedMemorySize, SMEM_BYTES);
    crf_kernel<<<B_, 128, SMEM_BYTES>>>(feats, trans, mask, tags, (float*)d_out);
}